// round 8
// baseline (speedup 1.0000x reference)
#include <cuda_runtime.h>
#include <cuda_fp16.h>
#include <cstdint>

#define HH    256
#define MT    128
#define NTH   512
#define CHOFF 0              // char fp16 tile 64KB (512B rows, swizzled)
#define WRING 65536          // 4 x 16KB W stages
#define GAOFF 131072         // gather -> aligned fp16 tile 64KB
#define CTL   196608
#define SMEM_SZ 197632

__device__ __half g_WT[2][256][512];   // W transposed [n][k] fp16

__device__ __forceinline__ uint32_t h2u(__half2 h) {
    return *reinterpret_cast<uint32_t*>(&h);
}
__device__ __forceinline__ uint32_t s2u(const void* p) {
    uint32_t a;
    asm("{ .reg .u64 t; cvta.to.shared.u64 t, %1; cvt.u32.u64 %0, t; }" : "=r"(a) : "l"(p));
    return a;
}
__device__ __forceinline__ void cpa16(uint32_t dst, const void* src) {
    asm volatile("cp.async.cg.shared.global [%0], [%1], 16;" :: "r"(dst), "l"(src));
}
__device__ __forceinline__ void ldsm4(uint32_t* r, uint32_t addr) {
    asm volatile("ldmatrix.sync.aligned.m8n8.x4.shared.b16 {%0,%1,%2,%3}, [%4];"
        : "=r"(r[0]), "=r"(r[1]), "=r"(r[2]), "=r"(r[3]) : "r"(addr));
}
__device__ __forceinline__ void mma16(float* d, const uint32_t* a, uint32_t b0, uint32_t b1) {
    asm volatile(
        "mma.sync.aligned.m16n8k16.row.col.f32.f16.f16.f32 "
        "{%0,%1,%2,%3}, {%4,%5,%6,%7}, {%8,%9}, {%0,%1,%2,%3};"
        : "+f"(d[0]), "+f"(d[1]), "+f"(d[2]), "+f"(d[3])
        : "r"(a[0]), "r"(a[1]), "r"(a[2]), "r"(a[3]), "r"(b0), "r"(b1));
}
__device__ __forceinline__ void sts32(uint32_t addr, uint32_t v) {
    asm volatile("st.shared.b32 [%0], %1;" :: "r"(addr), "r"(v));
}
__device__ __forceinline__ void sts64(uint32_t addr, uint32_t v0, uint32_t v1) {
    asm volatile("st.shared.v2.b32 [%0], {%1,%2};" :: "r"(addr), "r"(v0), "r"(v1));
}
__device__ __forceinline__ void sts128(uint32_t addr, uint32_t v0, uint32_t v1,
                                       uint32_t v2, uint32_t v3) {
    asm volatile("st.shared.v4.b32 [%0], {%1,%2,%3,%4};"
        :: "r"(addr), "r"(v0), "r"(v1), "r"(v2), "r"(v3));
}

// ---- prep: W[512][256] -> g_WT[w][256][512] fp16 ----
__global__ void prep_wt(const float* __restrict__ W1, const float* __restrict__ W2) {
    __shared__ float t[32][33];
    int b  = blockIdx.x;            // 2 w x 16 kt x 8 nt
    int w  = b & 1;
    int kt = (b >> 1) & 15;
    int nt = b >> 5;
    const float* W = w ? W2 : W1;
    int tx = threadIdx.x & 31, ty = threadIdx.x >> 5;
    #pragma unroll
    for (int p = 0; p < 4; p++) {
        int k = kt * 32 + ty + p * 8, n = nt * 32 + tx;
        t[ty + p * 8][tx] = W[k * 256 + n];
    }
    __syncthreads();
    #pragma unroll
    for (int p = 0; p < 4; p++) {
        int n = nt * 32 + ty + p * 8, k = kt * 32 + tx;
        g_WT[w][n][k] = __float2half_rn(t[tx][ty + p * 8]);
    }
}

// ---- stage s (0..31): W chunk [256n x 32k fp16] only ----
// phases: 0=W1 k[0,256)  1=W1 k[256,512)  2=W2 k[0,256)  3=W2 k[256,512)
__device__ __forceinline__ void stage_w(uint32_t sb, int tid, int s) {
    if (s < 32) {
        const int p0 = s >> 3;
        const int wk = (s & 7) * 32 + (p0 & 1) * 256;
        const int w  = p0 >> 1;
        const uint32_t base = sb + WRING + (uint32_t)(s & 3) * 16384;
        #pragma unroll
        for (int j = 0; j < 2; j++) {
            int gi = tid * 2 + j;
            int n = gi >> 2, c = gi & 3;
            cpa16(base + n * 64 + ((c ^ ((n >> 1) & 3)) << 4),
                  &g_WT[w][n][wk + c * 8]);
        }
    }
    asm volatile("cp.async.commit_group;" ::: "memory");
}

// ---- build a persistent fp16 tile (512B rows, (kk^row7) swizzle) from fp32 rows
__device__ __forceinline__ void build_row(uint32_t dst_base, int r,
                                          const float* __restrict__ src, int q)
{
    const float4* s4 = (const float4*)src;
    #pragma unroll
    for (int u = 0; u < 8; u++) {
        int kk = q * 8 + u;
        float4 v0 = s4[kk * 2], v1 = s4[kk * 2 + 1];
        uint32_t addr = dst_base + r * 512 + ((kk ^ (r & 7)) << 4);
        sts128(addr,
               h2u(__floats2half2_rn(v0.x, v0.y)), h2u(__floats2half2_rn(v0.z, v0.w)),
               h2u(__floats2half2_rn(v1.x, v1.y)), h2u(__floats2half2_rn(v1.z, v1.w)));
    }
}

__global__ __launch_bounds__(NTH, 1)
void syl_k(const float* __restrict__ ce, const void* __restrict__ ta,
           const float* __restrict__ dh,
           const float* __restrict__ b1v, const float* __restrict__ b2v,
           const float* __restrict__ gam, const float* __restrict__ bet,
           float* __restrict__ out)
{
    extern __shared__ char smem[];
    const uint32_t sb = s2u(smem);
    const int tid = threadIdx.x, lane = tid & 31, wid = tid >> 5;
    const int wm = wid >> 2, wn = wid & 3;           // 4m x 4n warp grid
    const int g = lane >> 2, tg = lane & 3;
    const int row0 = blockIdx.x * MT;
    int* sidx = (int*)(smem + CTL);
    int* sis  = (int*)(smem + CTL + 512);

    // dtype sniff (int32 vs int64 token_alignment)
    if (wid == 0) {
        const int2* p = (const int2*)ta;
        int2 v = p[lane];
        int ok = (v.y == 0 && v.x >= 0) || (v.y == -1 && v.x < 0);
        ok = __all_sync(0xffffffffu, ok);
        if (lane == 0) *sis = ok;
    }
    __syncthreads();
    if (tid < MT) {
        int gr = row0 + tid;
        long long idx = (*sis) ? ((const long long*)ta)[gr]
                               : (long long)((const int*)ta)[gr];
        int so = -1;
        if (idx >= 0) { int ii = (int)idx; if (ii > 2047) ii = 2047; so = (gr >> 14) * 2048 + ii; }
        sidx[tid] = so;
    }

    // kick off first 3 W stages, then build tiles under them
    stage_w(sb, tid, 0);
    stage_w(sb, tid, 1);
    stage_w(sb, tid, 2);
    __syncthreads();   // sidx visible

    // build char + gather tiles (4 threads per row, 64 cols each)
    {
        const int r = tid >> 2, q = tid & 3;
        build_row(sb + CHOFF, r, ce + (size_t)(row0 + r) * HH, q);
        int so = sidx[r];
        if (so >= 0) {
            build_row(sb + GAOFF, r, dh + (size_t)so * HH, q);
        } else {
            #pragma unroll
            for (int u = 0; u < 8; u++) {
                int kk = q * 8 + u;
                sts128(sb + GAOFF + r * 512 + ((kk ^ (r & 7)) << 4), 0u, 0u, 0u, 0u);
            }
        }
    }

    // LDSM geometry (validated mapping)
    const int t7   = lane & 7;
    const int rowA = ((lane & 8) ? 8 : 0) + t7;
    const int hiA  = (lane & 16) ? 1 : 0;
    const int rowB = ((lane & 16) ? 8 : 0) + t7;
    const int hiB  = (lane & 8) ? 1 : 0;
    const int f4   = (lane >> 1) & 3;
    uint32_t aT[2], bOff[4];
    #pragma unroll
    for (int mi = 0; mi < 2; mi++)
        aT[mi] = (uint32_t)(wm * 32 + mi * 16 + rowA) * 512;
    #pragma unroll
    for (int p = 0; p < 4; p++)
        bOff[p] = (uint32_t)(wn * 64 + p * 16 + rowB) * 64;

    float acc[2][8][4];
    #pragma unroll
    for (int mi = 0; mi < 2; mi++)
        #pragma unroll
        for (int ni = 0; ni < 8; ni++)
            #pragma unroll
            for (int c = 0; c < 4; c++) acc[mi][ni][c] = 0.f;

    __syncthreads();   // tiles built

    #pragma unroll 1
    for (int s = 0; s < 32; s++) {
        asm volatile("cp.async.wait_group 2;" ::: "memory");
        __syncthreads();

        stage_w(sb, tid, s + 3);

        // ---- compute(s): A from persistent tile, B from ring ----
        {
            const int p0 = s >> 3;
            const uint32_t abase = sb + ((p0 & 1) ? GAOFF : CHOFF);
            const uint32_t wbase = sb + WRING + (uint32_t)(s & 3) * 16384;
            #pragma unroll
            for (int ks = 0; ks < 2; ks++) {
                uint32_t a[2][4], b[4][4];
                uint32_t kk  = (uint32_t)((s & 7) * 4 + ks * 2 + hiA);
                uint32_t swa = (uint32_t)((kk ^ (uint32_t)t7) << 4);
                #pragma unroll
                for (int mi = 0; mi < 2; mi++) ldsm4(a[mi], abase + aT[mi] + swa);
                uint32_t swb = (uint32_t)(((ks * 2 + hiB) ^ f4) << 4);
                #pragma unroll
                for (int p = 0; p < 4; p++) ldsm4(b[p], wbase + bOff[p] + swb);
                #pragma unroll
                for (int mi = 0; mi < 2; mi++)
                    #pragma unroll
                    for (int ni = 0; ni < 8; ni++)
                        mma16(acc[mi][ni], a[mi],
                              b[ni >> 1][(ni & 1) * 2], b[ni >> 1][(ni & 1) * 2 + 1]);
            }
        }

        if (s == 15) {
            // all warps done reading gather tile before overlay
            __syncthreads();
            // epilogue 1: aligned = fp16(acc + b1) -> GA tile (swizzled)
            #pragma unroll
            for (int mi = 0; mi < 2; mi++)
                #pragma unroll
                for (int ni = 0; ni < 8; ni++) {
                    int col = wn * 64 + ni * 8 + tg * 2;
                    float2 bb = *(const float2*)(b1v + col);
                    #pragma unroll
                    for (int cp = 0; cp < 2; cp++) {
                        int row = wm * 32 + mi * 16 + g + 8 * cp;
                        __half2 h = __floats2half2_rn(acc[mi][ni][2 * cp]     + bb.x,
                                                      acc[mi][ni][2 * cp + 1] + bb.y);
                        uint32_t addr = sb + GAOFF + row * 512
                                      + ((((col >> 3) ^ (row & 7)) << 4) | ((col & 7) * 2));
                        sts32(addr, h2u(h));
                    }
                }
            #pragma unroll
            for (int mi = 0; mi < 2; mi++)
                #pragma unroll
                for (int ni = 0; ni < 8; ni++)
                    #pragma unroll
                    for (int c = 0; c < 4; c++) acc[mi][ni][c] = 0.f;
        }
    }
    __syncthreads();   // all LDSM reads done; char+ring regions now dead

    // ---- epilogue 2: feats(fp32) = acc + b2 -> smem bytes [0,128K), 1KB rows ----
    #pragma unroll
    for (int mi = 0; mi < 2; mi++)
        #pragma unroll
        for (int ni = 0; ni < 8; ni++) {
            int col = wn * 64 + ni * 8 + tg * 2;
            float2 bb = *(const float2*)(b2v + col);
            #pragma unroll
            for (int cp = 0; cp < 2; cp++) {
                int row = wm * 32 + mi * 16 + g + 8 * cp;
                uint32_t addr = sb + row * 1024 + col * 4;
                sts64(addr,
                      __float_as_uint(acc[mi][ni][2 * cp]     + bb.x),
                      __float_as_uint(acc[mi][ni][2 * cp + 1] + bb.y));
            }
        }
    __syncthreads();

    // ---- LayerNorm + exact GELU + residual (warp per row, 8 rows/warp) ----
    float* F = (float*)smem;
    #pragma unroll 1
    for (int rr = 0; rr < 8; rr++) {
        int r = wid * 8 + rr;
        const float* Frow = F + r * 256;
        float x[8];
        float sm = 0.f, q = 0.f;
        #pragma unroll
        for (int j = 0; j < 8; j++) {
            x[j] = Frow[lane + 32 * j];
            sm += x[j]; q += x[j] * x[j];
        }
        #pragma unroll
        for (int o = 16; o; o >>= 1) {
            sm += __shfl_xor_sync(0xffffffffu, sm, o);
            q  += __shfl_xor_sync(0xffffffffu, q, o);
        }
        float mu  = sm * (1.0f / HH);
        float var = q * (1.0f / HH) - mu * mu;
        float rs  = rsqrtf(var + 1e-5f);
        size_t gb = (size_t)(row0 + r) * HH;
        #pragma unroll
        for (int j = 0; j < 8; j++) {
            int cc = lane + 32 * j;
            float v = (x[j] - mu) * rs * __ldg(gam + cc) + __ldg(bet + cc);
            float gel = 0.5f * v * (1.0f + erff(v * 0.70710678118654752440f));
            out[gb + cc] = ce[gb + cc] + gel;
        }
    }
}

extern "C" void kernel_launch(void* const* d_in, const int* in_sizes, int n_in,
                              void* d_out, int out_size)
{
    const float* ce    = (const float*)d_in[0];
    const void*  ta    = d_in[1];
    const float* dh    = (const float*)d_in[2];
    const float* W1    = (const float*)d_in[3];
    const float* b1    = (const float*)d_in[4];
    const float* W2    = (const float*)d_in[5];
    const float* b2    = (const float*)d_in[6];
    const float* gamma = (const float*)d_in[7];
    const float* beta  = (const float*)d_in[8];
    float* out = (float*)d_out;

    int M = in_sizes[0] / HH;     // 131072 rows
    int grid = M / MT;            // 1024 CTAs

    prep_wt<<<256, 256>>>(W1, W2);

    cudaFuncSetAttribute(syl_k, cudaFuncAttributeMaxDynamicSharedMemorySize, SMEM_SZ);
    syl_k<<<grid, NTH, SMEM_SZ>>>(ce, ta, dh, b1, b2, gamma, beta, out);
}